// round 9
// baseline (speedup 1.0000x reference)
#include <cuda_runtime.h>
#include <cuda_fp16.h>

// ZINB decoder over 3M edges.
// Stage 1 (one launch): fp32->fp16 feature tables AND per-edge pre-gather of
//   {cs[u_e], gs[v_e]} into a contiguous float2 table. The scattered scalar
//   gathers (2 random lines/edge — as costly as the feature rows themselves)
//   move into this pure-gather kernel that runs near the wavefront floor.
// Stage 2: persistent kernel; warp = 16 consecutive edges/iter, 4 sets x 4
//   groups (8 lanes/edge), f32x2 packed-FMA dots, reduce-scatter (12 SHFL),
//   16-lane fast-math epilogue, coalesced stores; index prefetch pipeline.
//   cs/gs now arrive via ONE contiguous 128B line per warp-iteration.

#define BLOCK 256
#define N_CELLS_MAX 50000
#define N_GENES_MAX 20000
#define N_EDGES_MAX 3000000

__device__ __align__(16) static __half c_half_tbl[N_CELLS_MAX * 64];
__device__ __align__(16) static __half g_half_tbl[N_GENES_MAX * 64];
__device__ __align__(8)  static float2 csgs_tbl[N_EDGES_MAX];

typedef unsigned long long u64;

__device__ __forceinline__ u64 pack2(float x, float y) {
    u64 r; asm("mov.b64 %0, {%1,%2};" : "=l"(r) : "f"(x), "f"(y)); return r;
}
__device__ __forceinline__ u64 fma2(u64 a, u64 b, u64 c) {
    u64 d; asm("fma.rn.f32x2 %0, %1, %2, %3;" : "=l"(d) : "l"(a), "l"(b), "l"(c)); return d;
}
__device__ __forceinline__ float unpack_sum(u64 v) {
    float lo, hi; asm("mov.b64 {%0,%1}, %2;" : "=f"(lo), "=f"(hi) : "l"(v));
    return lo + hi;
}
__device__ __forceinline__ unsigned int h2_as_u32(__half2 h) {
    return *reinterpret_cast<unsigned int*>(&h);
}

// Fused prologue: fp16 conversion of both tables + per-edge cs/gs pre-gather.
__global__ __launch_bounds__(256)
void prologue_kernel(const float* __restrict__ cfeat, __half* __restrict__ cdst, int c_n8,
                     const float* __restrict__ gfeat, __half* __restrict__ gdst, int g_n8,
                     const int* __restrict__ edge_u, const int* __restrict__ edge_v,
                     const float* __restrict__ cs_factor, const float* __restrict__ gs_factor,
                     float2* __restrict__ csgs, int n_edges)
{
    const int i = blockIdx.x * blockDim.x + threadIdx.x;
    if (i < c_n8 + g_n8) {
        const float* src; __half* dst; int j;
        if (i < c_n8) { src = cfeat; dst = cdst; j = i; }
        else          { src = gfeat; dst = gdst; j = i - c_n8; }
        const float4* s = reinterpret_cast<const float4*>(src) + 2 * (size_t)j;
        const float4 a = s[0], b = s[1];
        uint4 o;
        o.x = h2_as_u32(__floats2half2_rn(a.x, a.y));
        o.y = h2_as_u32(__floats2half2_rn(a.z, a.w));
        o.z = h2_as_u32(__floats2half2_rn(b.x, b.y));
        o.w = h2_as_u32(__floats2half2_rn(b.z, b.w));
        reinterpret_cast<uint4*>(dst)[j] = o;
    } else {
        const int e = i - c_n8 - g_n8;
        if (e < n_edges) {
            const int u = edge_u[e];
            const int v = edge_v[e];
            csgs[e] = make_float2(cs_factor[u], gs_factor[v]);
        }
    }
}

__global__ __launch_bounds__(BLOCK)
void zinb_decoder_kernel(const __half* __restrict__ c_feat,
                         const __half* __restrict__ g_feat,
                         const float2* __restrict__ csgs,
                         const int*   __restrict__ edge_u,
                         const int*   __restrict__ edge_v,
                         const float* __restrict__ W_mean,
                         const float* __restrict__ b_mean,
                         const float* __restrict__ W_disp,
                         const float* __restrict__ b_disp,
                         const float* __restrict__ W_pi,
                         const float* __restrict__ b_pi,
                         float* __restrict__ out,
                         int n_edges)
{
    const unsigned FULL = 0xffffffffu;
    const int warpLane = threadIdx.x & 31;
    const int grp      = warpLane >> 3;    // 0..3
    const int lane8    = warpLane & 7;     // owns dims lane8*8 .. lane8*8+7

    // epilogue set id: s = 2*bit2 + bit1 (same for lane pairs {2k,2k+1})
    const int sl = ((warpLane & 4) >> 1) | ((warpLane & 2) >> 1);
    const int eoOff = 4 * sl + grp;        // this lane's epilogue edge offset in tile

    // ---- weights packed as f32x2, biases (registers, loaded once) ----
    const float4* wmv = reinterpret_cast<const float4*>(W_mean) + lane8 * 2;
    const float4* wdv = reinterpret_cast<const float4*>(W_disp) + lane8 * 2;
    const float4* wpv = reinterpret_cast<const float4*>(W_pi)   + lane8 * 2;
    const float4 a0 = __ldg(wmv), a1 = __ldg(wmv + 1);
    const float4 d0 = __ldg(wdv), d1 = __ldg(wdv + 1);
    const float4 p0 = __ldg(wpv), p1 = __ldg(wpv + 1);
    const u64 wm0 = pack2(a0.x, a0.y), wm1 = pack2(a0.z, a0.w),
              wm2 = pack2(a1.x, a1.y), wm3 = pack2(a1.z, a1.w);
    const u64 wd0 = pack2(d0.x, d0.y), wd1 = pack2(d0.z, d0.w),
              wd2 = pack2(d1.x, d1.y), wd3 = pack2(d1.z, d1.w);
    const u64 wp0 = pack2(p0.x, p0.y), wp1 = pack2(p0.z, p0.w),
              wp2 = pack2(p1.x, p1.y), wp3 = pack2(p1.z, p1.w);
    const float bm = __ldg(b_mean), bd = __ldg(b_disp), bp = __ldg(b_pi);

    const int warpId  = (blockIdx.x * BLOCK + threadIdx.x) >> 5;
    const int nWarps  = gridDim.x * (BLOCK >> 5);
    const int tileStr = nWarps * 16;

    const uint4* ctab = reinterpret_cast<const uint4*>(c_feat);
    const uint4* gtab = reinterpret_cast<const uint4*>(g_feat);

    int ebase = warpId * 16;
    if (ebase >= n_edges) return;

    // ---- prime index pipeline for the first tile ----
    int u0, v0, u1, v1, u2, v2, u3, v3;
    {
        const int e0 = ebase + grp;
        const int ec0 = e0      < n_edges ? e0      : 0;
        const int ec1 = e0 + 4  < n_edges ? e0 + 4  : 0;
        const int ec2 = e0 + 8  < n_edges ? e0 + 8  : 0;
        const int ec3 = e0 + 12 < n_edges ? e0 + 12 : 0;
        u0 = edge_u[ec0]; v0 = edge_v[ec0];
        u1 = edge_u[ec1]; v1 = edge_v[ec1];
        u2 = edge_u[ec2]; v2 = edge_v[ec2];
        u3 = edge_u[ec3]; v3 = edge_v[ec3];
    }

    for (; ebase < n_edges; ebase += tileStr) {
        // ---- feature gathers for CURRENT tile (indices already resident) ----
        const uint4 C0 = ctab[(size_t)u0 * 8 + lane8];
        const uint4 G0 = gtab[(size_t)v0 * 8 + lane8];
        const uint4 C1 = ctab[(size_t)u1 * 8 + lane8];
        const uint4 G1 = gtab[(size_t)v1 * 8 + lane8];
        const uint4 C2 = ctab[(size_t)u2 * 8 + lane8];
        const uint4 G2 = gtab[(size_t)v2 * 8 + lane8];
        const uint4 C3 = ctab[(size_t)u3 * 8 + lane8];
        const uint4 G3 = gtab[(size_t)v3 * 8 + lane8];

        // ---- cs/gs: CONTIGUOUS pre-gathered float2 (one 128B line/warp-iter) ----
        const int eo = ebase + eoOff;
        const float2 CG = csgs[eo < n_edges ? eo : 0];   // .x = cs, .y = gs

        // ---- PREFETCH indices for NEXT tile (overlaps compute below) ----
        int nu0, nv0, nu1, nv1, nu2, nv2, nu3, nv3;
        {
            const int e0 = ebase + tileStr + grp;
            const int ec0 = e0      < n_edges ? e0      : 0;
            const int ec1 = e0 + 4  < n_edges ? e0 + 4  : 0;
            const int ec2 = e0 + 8  < n_edges ? e0 + 8  : 0;
            const int ec3 = e0 + 12 < n_edges ? e0 + 12 : 0;
            nu0 = edge_u[ec0]; nv0 = edge_v[ec0];
            nu1 = edge_u[ec1]; nv1 = edge_v[ec1];
            nu2 = edge_u[ec2]; nv2 = edge_v[ec2];
            nu3 = edge_u[ec3]; nv3 = edge_v[ec3];
        }

        float m[4], d[4], p[4];
        #pragma unroll
        for (int s = 0; s < 4; s++) {
            const uint4& C = s == 0 ? C0 : s == 1 ? C1 : s == 2 ? C2 : C3;
            const uint4& G = s == 0 ? G0 : s == 1 ? G1 : s == 2 ? G2 : G3;
            const __half2* ch = reinterpret_cast<const __half2*>(&C);
            const __half2* gh = reinterpret_cast<const __half2*>(&G);
            const float2 q0 = __half22float2(__hmul2(ch[0], gh[0]));
            const float2 q1 = __half22float2(__hmul2(ch[1], gh[1]));
            const float2 q2 = __half22float2(__hmul2(ch[2], gh[2]));
            const float2 q3 = __half22float2(__hmul2(ch[3], gh[3]));
            const u64 h0 = pack2(q0.x, q0.y), h1 = pack2(q1.x, q1.y);
            const u64 h2 = pack2(q2.x, q2.y), h3 = pack2(q3.x, q3.y);
            u64 am = fma2(h0, wm0, fma2(h1, wm1, fma2(h2, wm2, fma2(h3, wm3, 0ull))));
            u64 ad = fma2(h0, wd0, fma2(h1, wd1, fma2(h2, wd2, fma2(h3, wd3, 0ull))));
            u64 ap = fma2(h0, wp0, fma2(h1, wp1, fma2(h2, wp2, fma2(h3, wp3, 0ull))));
            m[s] = unpack_sum(am);
            d[s] = unpack_sum(ad);
            p[s] = unpack_sum(ap);
        }

        // ---- reduce-scatter across 8 lanes: 12 SHFL total ----
        const bool hi4 = (warpLane & 4) != 0;
        float Am = hi4 ? m[2] : m[0], Ad = hi4 ? d[2] : d[0], Ap = hi4 ? p[2] : p[0];
        float Bm = hi4 ? m[3] : m[1], Bd = hi4 ? d[3] : d[1], Bp = hi4 ? p[3] : p[1];
        Am += __shfl_xor_sync(FULL, hi4 ? m[0] : m[2], 4);
        Ad += __shfl_xor_sync(FULL, hi4 ? d[0] : d[2], 4);
        Ap += __shfl_xor_sync(FULL, hi4 ? p[0] : p[2], 4);
        Bm += __shfl_xor_sync(FULL, hi4 ? m[1] : m[3], 4);
        Bd += __shfl_xor_sync(FULL, hi4 ? d[1] : d[3], 4);
        Bp += __shfl_xor_sync(FULL, hi4 ? p[1] : p[3], 4);
        const bool hi2 = (warpLane & 2) != 0;
        float Rm = hi2 ? Bm : Am, Rd = hi2 ? Bd : Ad, Rp = hi2 ? Bp : Ap;
        Rm += __shfl_xor_sync(FULL, hi2 ? Am : Bm, 2);
        Rd += __shfl_xor_sync(FULL, hi2 ? Ad : Bd, 2);
        Rp += __shfl_xor_sync(FULL, hi2 ? Ap : Bp, 2);
        Rm += __shfl_xor_sync(FULL, Rm, 1);
        Rd += __shfl_xor_sync(FULL, Rd, 1);
        Rp += __shfl_xor_sync(FULL, Rp, 1);

        // ---- epilogue: 16 even lanes, one edge each ----
        if ((warpLane & 1) == 0 && eo < n_edges) {
            const float mu_ = __fdividef(1.0f, 1.0f + __expf(-(Rm + bm)));
            const float pi  = __fdividef(1.0f, 1.0f + __expf(-(Rp + bp)));

            const float x  = CG.y * (Rd + bd);
            const float sx = fmaxf(x, 0.0f) + __logf(1.0f + __expf(-fabsf(x)));
            const float disp = fminf(fmaxf(sx, 1e-4f), 1e4f);

            const float mu = CG.x * fminf(fmaxf(__expf(CG.y * mu_) - 1.0f, 1e-5f), 1e6f);

            out[eo]                       = mu;
            out[(size_t)n_edges + eo]     = disp;
            out[(size_t)2 * n_edges + eo] = pi;
        }

        // ---- rotate prefetched indices in ----
        u0 = nu0; v0 = nv0; u1 = nu1; v1 = nv1;
        u2 = nu2; v2 = nv2; u3 = nu3; v3 = nv3;
    }
}

extern "C" void kernel_launch(void* const* d_in, const int* in_sizes, int n_in,
                              void* d_out, int out_size) {
    const float* c_feat    = (const float*)d_in[0];
    const float* g_feat    = (const float*)d_in[1];
    const float* cs_factor = (const float*)d_in[2];
    const float* gs_factor = (const float*)d_in[3];
    const int*   edge_u    = (const int*)d_in[4];
    const int*   edge_v    = (const int*)d_in[5];
    const float* W_mean    = (const float*)d_in[6];
    const float* b_mean    = (const float*)d_in[7];
    const float* W_disp    = (const float*)d_in[8];
    const float* b_disp    = (const float*)d_in[9];
    const float* W_pi      = (const float*)d_in[10];
    const float* b_pi      = (const float*)d_in[11];

    const int n_edges = in_sizes[4];
    float* out = (float*)d_out;

    __half* c_h = nullptr;
    __half* g_h = nullptr;
    float2* csgs = nullptr;
    cudaGetSymbolAddress((void**)&c_h, c_half_tbl);
    cudaGetSymbolAddress((void**)&g_h, g_half_tbl);
    cudaGetSymbolAddress((void**)&csgs, csgs_tbl);

    const int c_n8 = in_sizes[0] / 8;
    const int g_n8 = in_sizes[1] / 8;
    const long long pro_threads = (long long)c_n8 + g_n8 + n_edges;
    prologue_kernel<<<(int)((pro_threads + 255) / 256), 256>>>(
        c_feat, c_h, c_n8, g_feat, g_h, g_n8,
        edge_u, edge_v, cs_factor, gs_factor, csgs, n_edges);

    const int blocks = 1184;  // 148 SMs * 8
    zinb_decoder_kernel<<<blocks, BLOCK>>>(
        c_h, g_h, csgs, edge_u, edge_v,
        W_mean, b_mean, W_disp, b_disp, W_pi, b_pi,
        out, n_edges);
}

// round 10
// speedup vs baseline: 1.1910x; 1.1910x over previous
#include <cuda_runtime.h>
#include <cuda_fp16.h>

// ZINB decoder over 3M edges.
// Stage 1: fused fp32 -> fp16 feature-table conversion (row = one 128B line).
// Stage 2: persistent kernel, warp = 16 consecutive edges/iter (4 sets x 4
//   groups, 8 lanes/edge). f32x2 packed-FMA dots, reduce-scatter (12 SHFL),
//   16-lane fast-math epilogue, coalesced stores. SOFTWARE PIPELINE:
//   feature loads run ONE tile ahead (double-buffered), index loads TWO tiles
//   ahead; loop unrolled x2 (ping/pong) so no register copies. cs/gs stay as
//   direct scattered gathers (tables are L1/L2-resident -> cheap hits; the R9
//   pre-gather table was DRAM-resident and regressed).

#define BLOCK 256
#define N_CELLS_MAX 50000
#define N_GENES_MAX 20000

__device__ __align__(16) static __half c_half_tbl[N_CELLS_MAX * 64];
__device__ __align__(16) static __half g_half_tbl[N_GENES_MAX * 64];

typedef unsigned long long u64;

__device__ __forceinline__ u64 pack2(float x, float y) {
    u64 r; asm("mov.b64 %0, {%1,%2};" : "=l"(r) : "f"(x), "f"(y)); return r;
}
__device__ __forceinline__ u64 fma2(u64 a, u64 b, u64 c) {
    u64 d; asm("fma.rn.f32x2 %0, %1, %2, %3;" : "=l"(d) : "l"(a), "l"(b), "l"(c)); return d;
}
__device__ __forceinline__ float unpack_sum(u64 v) {
    float lo, hi; asm("mov.b64 {%0,%1}, %2;" : "=f"(lo), "=f"(hi) : "l"(v));
    return lo + hi;
}
__device__ __forceinline__ unsigned int h2_as_u32(__half2 h) {
    return *reinterpret_cast<unsigned int*>(&h);
}

// Fused fp32 -> fp16 conversion for both tables (8 floats per thread).
__global__ __launch_bounds__(256)
void cvt_fp16_kernel(const float* __restrict__ srcA, __half* __restrict__ dstA, int nA8,
                     const float* __restrict__ srcB, __half* __restrict__ dstB, int nB8) {
    int i = blockIdx.x * blockDim.x + threadIdx.x;
    const float* src; __half* dst; int j;
    if (i < nA8) { src = srcA; dst = dstA; j = i; }
    else if (i < nA8 + nB8) { src = srcB; dst = dstB; j = i - nA8; }
    else return;
    const float4* s = reinterpret_cast<const float4*>(src) + 2 * (size_t)j;
    const float4 a = s[0], b = s[1];
    uint4 o;
    o.x = h2_as_u32(__floats2half2_rn(a.x, a.y));
    o.y = h2_as_u32(__floats2half2_rn(a.z, a.w));
    o.z = h2_as_u32(__floats2half2_rn(b.x, b.y));
    o.w = h2_as_u32(__floats2half2_rn(b.z, b.w));
    reinterpret_cast<uint4*>(dst)[j] = o;
}

struct IdxTile { int u0, v0, u1, v1, u2, v2, u3, v3; };
struct FeatTile { uint4 C0, G0, C1, G1, C2, G2, C3, G3; };

__device__ __forceinline__ IdxTile load_idx(const int* __restrict__ eu,
                                            const int* __restrict__ ev,
                                            int ebase, int grp, int n_edges) {
    const int e0 = ebase + grp;
    const int ec0 = (e0      < n_edges && e0      >= 0) ? e0      : 0;
    const int ec1 = (e0 + 4  < n_edges) ? e0 + 4  : 0;
    const int ec2 = (e0 + 8  < n_edges) ? e0 + 8  : 0;
    const int ec3 = (e0 + 12 < n_edges) ? e0 + 12 : 0;
    IdxTile t;
    t.u0 = eu[ec0]; t.v0 = ev[ec0];
    t.u1 = eu[ec1]; t.v1 = ev[ec1];
    t.u2 = eu[ec2]; t.v2 = ev[ec2];
    t.u3 = eu[ec3]; t.v3 = ev[ec3];
    return t;
}

__device__ __forceinline__ FeatTile load_feats(const uint4* __restrict__ ctab,
                                               const uint4* __restrict__ gtab,
                                               const IdxTile& ix, int lane8) {
    FeatTile f;
    f.C0 = ctab[(size_t)ix.u0 * 8 + lane8];
    f.G0 = gtab[(size_t)ix.v0 * 8 + lane8];
    f.C1 = ctab[(size_t)ix.u1 * 8 + lane8];
    f.G1 = gtab[(size_t)ix.v1 * 8 + lane8];
    f.C2 = ctab[(size_t)ix.u2 * 8 + lane8];
    f.G2 = gtab[(size_t)ix.v2 * 8 + lane8];
    f.C3 = ctab[(size_t)ix.u3 * 8 + lane8];
    f.G3 = gtab[(size_t)ix.v3 * 8 + lane8];
    return f;
}

__global__ __launch_bounds__(BLOCK, 2)
void zinb_decoder_kernel(const __half* __restrict__ c_feat,
                         const __half* __restrict__ g_feat,
                         const float* __restrict__ cs_factor,
                         const float* __restrict__ gs_factor,
                         const int*   __restrict__ edge_u,
                         const int*   __restrict__ edge_v,
                         const float* __restrict__ W_mean,
                         const float* __restrict__ b_mean,
                         const float* __restrict__ W_disp,
                         const float* __restrict__ b_disp,
                         const float* __restrict__ W_pi,
                         const float* __restrict__ b_pi,
                         float* __restrict__ out,
                         int n_edges)
{
    const unsigned FULL = 0xffffffffu;
    const int warpLane = threadIdx.x & 31;
    const int grp      = warpLane >> 3;
    const int lane8    = warpLane & 7;
    const int sl       = ((warpLane & 4) >> 1) | ((warpLane & 2) >> 1);
    const int eoOff    = 4 * sl + grp;

    // ---- weights packed as f32x2, biases ----
    const float4* wmv = reinterpret_cast<const float4*>(W_mean) + lane8 * 2;
    const float4* wdv = reinterpret_cast<const float4*>(W_disp) + lane8 * 2;
    const float4* wpv = reinterpret_cast<const float4*>(W_pi)   + lane8 * 2;
    const float4 a0 = __ldg(wmv), a1 = __ldg(wmv + 1);
    const float4 d0 = __ldg(wdv), d1 = __ldg(wdv + 1);
    const float4 p0 = __ldg(wpv), p1 = __ldg(wpv + 1);
    const u64 wm0 = pack2(a0.x, a0.y), wm1 = pack2(a0.z, a0.w),
              wm2 = pack2(a1.x, a1.y), wm3 = pack2(a1.z, a1.w);
    const u64 wd0 = pack2(d0.x, d0.y), wd1 = pack2(d0.z, d0.w),
              wd2 = pack2(d1.x, d1.y), wd3 = pack2(d1.z, d1.w);
    const u64 wp0 = pack2(p0.x, p0.y), wp1 = pack2(p0.z, p0.w),
              wp2 = pack2(p1.x, p1.y), wp3 = pack2(p1.z, p1.w);
    const float bm = __ldg(b_mean), bd = __ldg(b_disp), bp = __ldg(b_pi);

    const int warpId  = (blockIdx.x * BLOCK + threadIdx.x) >> 5;
    const int nWarps  = gridDim.x * (BLOCK >> 5);
    const int tileStr = nWarps * 16;

    const uint4* ctab = reinterpret_cast<const uint4*>(c_feat);
    const uint4* gtab = reinterpret_cast<const uint4*>(g_feat);

    const int e0 = warpId * 16;
    if (e0 >= n_edges) return;

    // ---- compute+store one tile (features + indices already resident) ----
    auto compute_store = [&](const FeatTile& F, const IdxTile& IX, int ebase) {
        // cs/gs scattered gathers: small L1/L2-resident tables -> cheap hits
        const int uSel = sl < 2 ? (sl == 0 ? IX.u0 : IX.u1) : (sl == 2 ? IX.u2 : IX.u3);
        const int vSel = sl < 2 ? (sl == 0 ? IX.v0 : IX.v1) : (sl == 2 ? IX.v2 : IX.v3);
        const float GS = gs_factor[vSel];
        const float CS = cs_factor[uSel];

        float m[4], d[4], p[4];
        #pragma unroll
        for (int s = 0; s < 4; s++) {
            const uint4& C = s == 0 ? F.C0 : s == 1 ? F.C1 : s == 2 ? F.C2 : F.C3;
            const uint4& G = s == 0 ? F.G0 : s == 1 ? F.G1 : s == 2 ? F.G2 : F.G3;
            const __half2* ch = reinterpret_cast<const __half2*>(&C);
            const __half2* gh = reinterpret_cast<const __half2*>(&G);
            const float2 q0 = __half22float2(__hmul2(ch[0], gh[0]));
            const float2 q1 = __half22float2(__hmul2(ch[1], gh[1]));
            const float2 q2 = __half22float2(__hmul2(ch[2], gh[2]));
            const float2 q3 = __half22float2(__hmul2(ch[3], gh[3]));
            const u64 h0 = pack2(q0.x, q0.y), h1 = pack2(q1.x, q1.y);
            const u64 h2 = pack2(q2.x, q2.y), h3 = pack2(q3.x, q3.y);
            u64 am = fma2(h0, wm0, fma2(h1, wm1, fma2(h2, wm2, fma2(h3, wm3, 0ull))));
            u64 ad = fma2(h0, wd0, fma2(h1, wd1, fma2(h2, wd2, fma2(h3, wd3, 0ull))));
            u64 ap = fma2(h0, wp0, fma2(h1, wp1, fma2(h2, wp2, fma2(h3, wp3, 0ull))));
            m[s] = unpack_sum(am);
            d[s] = unpack_sum(ad);
            p[s] = unpack_sum(ap);
        }

        // reduce-scatter across 8 lanes: 12 SHFL
        const bool hi4 = (warpLane & 4) != 0;
        float Am = hi4 ? m[2] : m[0], Ad = hi4 ? d[2] : d[0], Ap = hi4 ? p[2] : p[0];
        float Bm = hi4 ? m[3] : m[1], Bd = hi4 ? d[3] : d[1], Bp = hi4 ? p[3] : p[1];
        Am += __shfl_xor_sync(FULL, hi4 ? m[0] : m[2], 4);
        Ad += __shfl_xor_sync(FULL, hi4 ? d[0] : d[2], 4);
        Ap += __shfl_xor_sync(FULL, hi4 ? p[0] : p[2], 4);
        Bm += __shfl_xor_sync(FULL, hi4 ? m[1] : m[3], 4);
        Bd += __shfl_xor_sync(FULL, hi4 ? d[1] : d[3], 4);
        Bp += __shfl_xor_sync(FULL, hi4 ? p[1] : p[3], 4);
        const bool hi2 = (warpLane & 2) != 0;
        float Rm = hi2 ? Bm : Am, Rd = hi2 ? Bd : Ad, Rp = hi2 ? Bp : Ap;
        Rm += __shfl_xor_sync(FULL, hi2 ? Am : Bm, 2);
        Rd += __shfl_xor_sync(FULL, hi2 ? Ad : Bd, 2);
        Rp += __shfl_xor_sync(FULL, hi2 ? Ap : Bp, 2);
        Rm += __shfl_xor_sync(FULL, Rm, 1);
        Rd += __shfl_xor_sync(FULL, Rd, 1);
        Rp += __shfl_xor_sync(FULL, Rp, 1);

        const int eo = ebase + eoOff;
        if ((warpLane & 1) == 0 && eo < n_edges) {
            const float mu_ = __fdividef(1.0f, 1.0f + __expf(-(Rm + bm)));
            const float pi  = __fdividef(1.0f, 1.0f + __expf(-(Rp + bp)));
            const float x   = GS * (Rd + bd);
            const float sx  = fmaxf(x, 0.0f) + __logf(1.0f + __expf(-fabsf(x)));
            const float disp = fminf(fmaxf(sx, 1e-4f), 1e4f);
            const float mu  = CS * fminf(fmaxf(__expf(GS * mu_) - 1.0f, 1e-5f), 1e6f);
            out[eo]                       = mu;
            out[(size_t)n_edges + eo]     = disp;
            out[(size_t)2 * n_edges + eo] = pi;
        }
    };

    // ---- prime pipeline: indices for tiles 0,1; features for tile 0 ----
    IdxTile ia = load_idx(edge_u, edge_v, e0,           grp, n_edges);
    IdxTile ib = load_idx(edge_u, edge_v, e0 + tileStr, grp, n_edges);
    FeatTile fa = load_feats(ctab, gtab, ia, lane8);

    for (int ebase = e0; ebase < n_edges; ebase += 2 * tileStr) {
        // phase A: prefetch tile t+1 features, tile t+2 indices; compute tile t
        FeatTile fb = load_feats(ctab, gtab, ib, lane8);
        IdxTile  ic = load_idx(edge_u, edge_v, ebase + 2 * tileStr, grp, n_edges);
        compute_store(fa, ia, ebase);

        // phase B: prefetch tile t+2 features, tile t+3 indices; compute tile t+1
        fa = load_feats(ctab, gtab, ic, lane8);
        IdxTile id = load_idx(edge_u, edge_v, ebase + 3 * tileStr, grp, n_edges);
        if (ebase + tileStr < n_edges)
            compute_store(fb, ib, ebase + tileStr);

        ia = ic; ib = id;
    }
}

extern "C" void kernel_launch(void* const* d_in, const int* in_sizes, int n_in,
                              void* d_out, int out_size) {
    const float* c_feat    = (const float*)d_in[0];
    const float* g_feat    = (const float*)d_in[1];
    const float* cs_factor = (const float*)d_in[2];
    const float* gs_factor = (const float*)d_in[3];
    const int*   edge_u    = (const int*)d_in[4];
    const int*   edge_v    = (const int*)d_in[5];
    const float* W_mean    = (const float*)d_in[6];
    const float* b_mean    = (const float*)d_in[7];
    const float* W_disp    = (const float*)d_in[8];
    const float* b_disp    = (const float*)d_in[9];
    const float* W_pi      = (const float*)d_in[10];
    const float* b_pi      = (const float*)d_in[11];

    const int n_edges = in_sizes[4];
    float* out = (float*)d_out;

    __half* c_h = nullptr;
    __half* g_h = nullptr;
    cudaGetSymbolAddress((void**)&c_h, c_half_tbl);
    cudaGetSymbolAddress((void**)&g_h, g_half_tbl);

    const int c_n8 = in_sizes[0] / 8;
    const int g_n8 = in_sizes[1] / 8;
    cvt_fp16_kernel<<<(c_n8 + g_n8 + 255) / 256, 256>>>(c_feat, c_h, c_n8,
                                                        g_feat, g_h, g_n8);

    const int blocks = 1184;  // 148 SMs * 8
    zinb_decoder_kernel<<<blocks, BLOCK>>>(
        c_h, g_h, cs_factor, gs_factor, edge_u, edge_v,
        W_mean, b_mean, W_disp, b_disp, W_pi, b_pi,
        out, n_edges);
}